// round 11
// baseline (speedup 1.0000x reference)
#include <cuda_runtime.h>
#include <cstdint>

// MPS classifier: logits[b] = unit(v_b @ prod_n M_n(b)) @ C^T + log||prod||
// R11 = R10 with the smem overflow fixed (transposed bufX, no padding:
// static smem back to 48896B < 48KB limit).
// Design: 4 threads per batch, each holding the FULL replicated v (5 f32x2).
// Thread `part` handles l ≡ part (mod 4): builds m for its l-rows from a
// near-broadcast smem table and accumulates partial w[10]; a 2-round
// 4-thread butterfly re-replicates w. Per warp-step: 20 SHFL.32 (was 160),
// rescale shuffle-free. Attacks the SM shuffle-unit wall identified in R9.
//
// Table layout per pair-step s: for l in 0..9, hq in 0..4, float4 at
// s*100 + l*10 + 2*hq + e:
//   e=0 (AB): (p00[l][2hq], p00[l][2hq+1], p10[l][2hq], p10[l][2hq+1])
//   e=1 (CD): (p01[l][2hq], p01[l][2hq+1], p11[l][2hq], p11[l][2hq+1])
// bufX is slot-major: float4 [vv][bi] at index vv*BPB+bi (conflict-free
// single-float reads across the 8 batches of a warp).

#define NSITE 783
#define NPAIR 392
#define CHUNK 14             // pairs per chunk
#define NCHUNK 28            // 392 / 14
#define BPB 16               // batches per block (2 warps x 8)
#define THREADS 64           // 2 warps
#define NBLOCK 128           // 128 * 16 = 2048 exactly
#define XV 8                 // x-float4 slots per batch per chunk

__device__ float4 g_pmat[NPAIR * 100];

__device__ __forceinline__ void cpasync16(void* dst_smem, const void* src) {
    uint32_t d = (uint32_t)__cvta_generic_to_shared(dst_smem);
    asm volatile("cp.async.cg.shared.global [%0], [%1], 16;" :: "r"(d), "l"(src) : "memory");
}
__device__ __forceinline__ uint64_t pack2(float lo, float hi) {
    uint64_t r;
    asm("mov.b64 %0, {%1, %2};" : "=l"(r) : "r"(__float_as_uint(lo)), "r"(__float_as_uint(hi)));
    return r;
}
__device__ __forceinline__ void unpack2(float& lo, float& hi, uint64_t v) {
    uint32_t a, b;
    asm("mov.b64 {%0, %1}, %2;" : "=r"(a), "=r"(b) : "l"(v));
    lo = __uint_as_float(a); hi = __uint_as_float(b);
}
__device__ __forceinline__ uint64_t fma2(uint64_t a, uint64_t b, uint64_t c) {
    uint64_t d;
    asm("fma.rn.f32x2 %0, %1, %2, %3;" : "=l"(d) : "l"(a), "l"(b), "l"(c));
    return d;
}
__device__ __forceinline__ uint64_t add2(uint64_t a, uint64_t b) {
    uint64_t d;
    asm("add.rn.f32x2 %0, %1, %2;" : "=l"(d) : "l"(a), "l"(b));
    return d;
}
__device__ __forceinline__ uint64_t mul2(uint64_t a, uint64_t b) {
    uint64_t d;
    asm("mul.rn.f32x2 %0, %1, %2;" : "=l"(d) : "l"(a), "l"(b));
    return d;
}
__device__ __forceinline__ float sum2(uint64_t v) {
    float lo, hi; unpack2(lo, hi, v); return lo + hi;
}

// ---------------------------------------------------------------------------
// Precompute pair matrices, packed by (l, h-pair). One block per pair.
// cores_mid layout: [n][l][f][h] -> ((l*2+f)*10 + h), n in [0,783)
// ---------------------------------------------------------------------------
__global__ void prep_pairs_kernel(const float* __restrict__ cm) {
    __shared__ float s1[200];
    __shared__ float s2[200];
    __shared__ float4 sP[100];   // (l,h) -> (p00, p10, p01, p11)
    int j = blockIdx.x;
    int t = threadIdx.x;
    int s2i = 2 * j + 1;
    if (t < 100) {
        const float* p1 = cm + (2 * j) * 200;
        s1[t]       = p1[t];
        s1[t + 100] = p1[t + 100];
        if (s2i < NSITE) {
            const float* p2 = cm + s2i * 200;
            s2[t]       = p2[t];
            s2[t + 100] = p2[t + 100];
        } else {
            #pragma unroll
            for (int q = t; q < 200; q += 100) {
                int l = q / 20;
                int h = q % 10;
                s2[q] = (l == h) ? 1.0f : 0.0f;   // identity pad (D2 = 0)
            }
        }
    }
    __syncthreads();
    if (t < 100) {
        int l = t / 10;
        int h = t % 10;
        float p00 = 0.f, p10 = 0.f, p01 = 0.f, p11 = 0.f;
        #pragma unroll
        for (int k = 0; k < 10; k++) {
            float a1 = s1[l * 20 + k];
            float d1 = s1[l * 20 + 10 + k] - a1;
            float a2 = s2[k * 20 + h];
            float d2 = s2[k * 20 + 10 + h] - a2;
            p00 = fmaf(a1, a2, p00);
            p10 = fmaf(d1, a2, p10);
            p01 = fmaf(a1, d2, p01);
            p11 = fmaf(d1, d2, p11);
        }
        sP[t] = make_float4(p00, p10, p01, p11);
    }
    __syncthreads();
    if (t < 100) {
        int l  = t / 10;
        int r  = t % 10;
        int hq = r >> 1;
        int e  = r & 1;
        float4 u0 = sP[l * 10 + 2 * hq];
        float4 u1 = sP[l * 10 + 2 * hq + 1];
        float4 o = (e == 0) ? make_float4(u0.x, u1.x, u0.y, u1.y)
                            : make_float4(u0.z, u1.z, u0.w, u1.w);
        g_pmat[j * 100 + l * 10 + 2 * hq + e] = o;
    }
}

// ---------------------------------------------------------------------------
// Main chain kernel. 64 threads = 2 warps = 16 batches (4 threads/batch).
// lane = (local_batch & 7)*4 + part; part handles l in {part, part+4, part+8<10}.
// ---------------------------------------------------------------------------
__global__ void __launch_bounds__(THREADS, 1) mps_chain_kernel(
    const float* __restrict__ x,      // [2048, 784]
    const float* __restrict__ core0,  // [1, 2, 10]
    const float* __restrict__ cls,    // [10, 10]
    float* __restrict__ out)          // [2048, 10]
{
    __shared__ float4 bufP[2][CHUNK * 100];   // 2 x 22.4 KB
    __shared__ float4 bufX[2][XV * BPB];      // 2 x 2 KB, slot-major [vv][bi]

    const unsigned FULL = 0xffffffffu;
    int tid    = threadIdx.x;
    int lane   = tid & 31;
    int warpid = tid >> 5;
    int part   = lane & 3;
    int bl     = warpid * 8 + (lane >> 2);        // local batch 0..15
    int b      = blockIdx.x * BPB + bl;
    bool pOdd  = (part & 1) != 0;
    bool pHi   = (part & 2) != 0;
    bool pLow  = part < 2;

    auto issue_chunk = [&](int c) {
        int pb = c & 1;
        int nvec = (c == NCHUNK - 1) ? 7 : XV;    // last chunk: 756+28 = 784
        const float4* psrc = g_pmat + c * (CHUNK * 100);
        for (int i = tid; i < CHUNK * 100 + BPB * XV; i += THREADS) {
            if (i < CHUNK * 100) {
                cpasync16(&bufP[pb][i], psrc + i);
            } else {
                int q  = i - CHUNK * 100;
                int bi = q >> 3, vv = q & 7;
                if (vv < nvec) {
                    cpasync16(&bufX[pb][vv * BPB + bi],
                              x + (size_t)(blockIdx.x * BPB + bi) * 784
                                + c * (2 * CHUNK) + vv * 4);
                }
            }
        }
        asm volatile("cp.async.commit_group;" ::: "memory");
    };

    // head: v[h] = core0[0,h] + t0*(core0[1,h]-core0[0,h]), replicated
    float t0 = __ldg(x + (size_t)b * 784);
    uint64_t w2[5];
    #pragma unroll
    for (int q = 0; q < 5; q++) {
        float a0 = __ldg(core0 + 2 * q),     b0 = __ldg(core0 + 10 + 2 * q);
        float a1 = __ldg(core0 + 2 * q + 1), b1 = __ldg(core0 + 11 + 2 * q);
        w2[q] = pack2(fmaf(t0, b0 - a0, a0), fmaf(t0, b1 - a1, a1));
    }
    int K = 0;

    issue_chunk(0);
    asm volatile("cp.async.wait_group 0;" ::: "memory");
    __syncthreads();

    for (int c = 0; c < NCHUNK; c++) {
        int pb = c & 1;
        if (c + 1 < NCHUNK) issue_chunk(c + 1);

        const ulonglong2* P2 = (const ulonglong2*)(&bufP[pb][0]);
        const float* txf = (const float*)(&bufX[pb][0]);
        // float index f of this batch's chunk-local x: txf[(f>>2)*BPB*4 + bl*4 + (f&3)]
        #define TXF(f) txf[((f) >> 2) * (BPB * 4) + bl * 4 + ((f) & 3)]

        #pragma unroll
        for (int jj = 0; jj < CHUNK; jj++) {
            // unpack replicated v and select this part's l-components
            float w10[10];
            #pragma unroll
            for (int q = 0; q < 5; q++) unpack2(w10[2 * q], w10[2 * q + 1], w2[q]);
            float vl0 = pHi ? (pOdd ? w10[3] : w10[2]) : (pOdd ? w10[1] : w10[0]);
            float vl1 = pHi ? (pOdd ? w10[7] : w10[6]) : (pOdd ? w10[5] : w10[4]);
            float vl2 = pOdd ? w10[9] : w10[8];   // used only when pLow

            // t-values (identity-padded pair s=391: slot 7 is not re-staged
            // in the last chunk — stale same-parity, finite; it multiplies
            // p01 = p11 = 0. Benign.)
            float t1 = TXF(2 * jj + 1), t2 = TXF(2 * jj + 2);
            uint64_t t1_2 = pack2(t1, t1), t2_2 = pack2(t2, t2);
            float c12 = t1 * t2;
            uint64_t c12_2 = pack2(c12, c12);

            uint64_t acc0 = 0, acc1 = 0, acc2 = 0, acc3 = 0, acc4 = 0;
            // i = 0: l = part
            {
                const ulonglong2* pl = P2 + jj * 100 + part * 10;
                uint64_t vv = pack2(vl0, vl0);
                #pragma unroll
                for (int hq = 0; hq < 5; hq++) {
                    ulonglong2 AB = pl[2 * hq];
                    ulonglong2 CD = pl[2 * hq + 1];
                    uint64_t m = fma2(t1_2, AB.y, AB.x);
                    m = fma2(t2_2, CD.x, m);
                    m = fma2(c12_2, CD.y, m);
                    uint64_t r = fma2(vv, m, (hq == 0) ? acc0 : (hq == 1) ? acc1 : (hq == 2) ? acc2 : (hq == 3) ? acc3 : acc4);
                    if (hq == 0) acc0 = r; else if (hq == 1) acc1 = r; else if (hq == 2) acc2 = r; else if (hq == 3) acc3 = r; else acc4 = r;
                }
            }
            // i = 1: l = part + 4
            {
                const ulonglong2* pl = P2 + jj * 100 + (part + 4) * 10;
                uint64_t vv = pack2(vl1, vl1);
                #pragma unroll
                for (int hq = 0; hq < 5; hq++) {
                    ulonglong2 AB = pl[2 * hq];
                    ulonglong2 CD = pl[2 * hq + 1];
                    uint64_t m = fma2(t1_2, AB.y, AB.x);
                    m = fma2(t2_2, CD.x, m);
                    m = fma2(c12_2, CD.y, m);
                    uint64_t r = fma2(vv, m, (hq == 0) ? acc0 : (hq == 1) ? acc1 : (hq == 2) ? acc2 : (hq == 3) ? acc3 : acc4);
                    if (hq == 0) acc0 = r; else if (hq == 1) acc1 = r; else if (hq == 2) acc2 = r; else if (hq == 3) acc3 = r; else acc4 = r;
                }
            }
            // i = 2: l = part + 8 (parts 0,1 only)
            if (pLow) {
                const ulonglong2* pl = P2 + jj * 100 + (part + 8) * 10;
                uint64_t vv = pack2(vl2, vl2);
                #pragma unroll
                for (int hq = 0; hq < 5; hq++) {
                    ulonglong2 AB = pl[2 * hq];
                    ulonglong2 CD = pl[2 * hq + 1];
                    uint64_t m = fma2(t1_2, AB.y, AB.x);
                    m = fma2(t2_2, CD.x, m);
                    m = fma2(c12_2, CD.y, m);
                    uint64_t r = fma2(vv, m, (hq == 0) ? acc0 : (hq == 1) ? acc1 : (hq == 2) ? acc2 : (hq == 3) ? acc3 : acc4);
                    if (hq == 0) acc0 = r; else if (hq == 1) acc1 = r; else if (hq == 2) acc2 = r; else if (hq == 3) acc3 = r; else acc4 = r;
                }
            }

            // butterfly over the 4-thread group: re-replicates full w
            #pragma unroll
            for (int d = 1; d <= 2; d <<= 1) {
                acc0 = add2(acc0, (uint64_t)__shfl_xor_sync(FULL, (unsigned long long)acc0, d));
                acc1 = add2(acc1, (uint64_t)__shfl_xor_sync(FULL, (unsigned long long)acc1, d));
                acc2 = add2(acc2, (uint64_t)__shfl_xor_sync(FULL, (unsigned long long)acc2, d));
                acc3 = add2(acc3, (uint64_t)__shfl_xor_sync(FULL, (unsigned long long)acc3, d));
                acc4 = add2(acc4, (uint64_t)__shfl_xor_sync(FULL, (unsigned long long)acc4, d));
            }
            w2[0] = acc0; w2[1] = acc1; w2[2] = acc2; w2[3] = acc3; w2[4] = acc4;
        }
        #undef TXF

        // exact power-of-2 rescale (shuffle-free: v is replicated per thread)
        {
            uint64_t ss2 = 0;
            #pragma unroll
            for (int q = 0; q < 5; q++) ss2 = fma2(w2[q], w2[q], ss2);
            float ss = sum2(ss2);
            int sh = (((__float_as_int(ss) >> 23) & 0xff) - 127) >> 1;
            K += sh;
            float sc = __int_as_float((127 - sh) << 23);
            uint64_t sc2 = pack2(sc, sc);
            #pragma unroll
            for (int q = 0; q < 5; q++) w2[q] = mul2(w2[q], sc2);
        }

        if (c + 1 < NCHUNK)
            asm volatile("cp.async.wait_group 0;" ::: "memory");
        __syncthreads();
    }

    // final norm + single log
    float ss;
    {
        uint64_t ss2 = 0;
        #pragma unroll
        for (int q = 0; q < 5; q++) ss2 = fma2(w2[q], w2[q], ss2);
        ss = sum2(ss2);
    }
    float na = fmaxf(sqrtf(ss), 1e-30f);
    float lognorm = (float)K * 0.69314718055994531f + __logf(na);
    float inv = 1.0f / na;
    float w10[10];
    #pragma unroll
    for (int q = 0; q < 5; q++) {
        unpack2(w10[2 * q], w10[2 * q + 1], w2[q]);
        w10[2 * q] *= inv; w10[2 * q + 1] *= inv;
    }

    // outputs: part writes classes {part, part+4} and part+8 (parts 0,1)
    #pragma unroll
    for (int i = 0; i < 3; i++) {
        int o = part + 4 * i;
        if (o < 10) {
            float acc = lognorm;
            #pragma unroll
            for (int hh = 0; hh < 10; hh++)
                acc = fmaf(w10[hh], __ldg(cls + o * 10 + hh), acc);
            out[(size_t)b * 10 + o] = acc;
        }
    }
}

// ---------------------------------------------------------------------------
extern "C" void kernel_launch(void* const* d_in, const int* in_sizes, int n_in,
                              void* d_out, int out_size) {
    const float* x     = (const float*)d_in[0];  // [2048, 784]
    const float* core0 = (const float*)d_in[1];  // [1, 2, 10]
    const float* cm    = (const float*)d_in[2];  // [783, 10, 2, 10]
    const float* cls   = (const float*)d_in[3];  // [10, 10]
    float* out = (float*)d_out;                  // [2048, 10]

    prep_pairs_kernel<<<NPAIR, 128>>>(cm);
    mps_chain_kernel<<<NBLOCK, THREADS>>>(x, core0, cls, out);
}